// round 2
// baseline (speedup 1.0000x reference)
#include <cuda_runtime.h>
#include <math.h>

#define NPTS  32768      // 32*32*32 spatial points
#define CIN   64         // input channels (Cf = Cm)
#define NHD   16         // heads
#define HD    64         // head dim
#define CQ    1024       // NHD*HD
#define LNEPS 1e-5f

typedef unsigned long long ull;

// ---------------- f32x2 packed-FMA helpers ----------------
__device__ __forceinline__ ull pack2(float a, float b) {
    ull r; asm("mov.b64 %0,{%1,%2};" : "=l"(r) : "f"(a), "f"(b)); return r;
}
__device__ __forceinline__ void fma2(ull& d, ull a, ull b) {
    asm("fma.rn.f32x2 %0,%1,%2,%0;" : "+l"(d) : "l"(a), "l"(b));
}
__device__ __forceinline__ float2 unpack2(ull v) {
    float2 f; asm("mov.b64 {%0,%1},%2;" : "=f"(f.x), "=f"(f.y) : "l"(v)); return f;
}

// ---------------- scratch ----------------
__device__ float g_xf[NPTS * CIN];     // LN(F), layout [p][c]
__device__ float g_xm[NPTS * CIN];     // LN(M), layout [p][c]
__device__ float g_qm[NPTS * CQ];      // qm, float4-chunked: [(h*16+c4)][p][4]
__device__ float g_G [CIN * CQ];       // G[i][h*64+j] = sum_d wf[i][h*64+d]*wm[j][h*64+d]
__device__ float g_u [CQ];             // u[h*64+j]    = sum_d wm[j][h*64+d]*bf[h*64+d]

// ---------------- kernel 0: per-head fused weight matrices ----------------
__global__ __launch_bounds__(256) void precompute_kernel(
    const float* __restrict__ wf, const float* __restrict__ wm,
    const float* __restrict__ bf)
{
    int h = blockIdx.x;
    __shared__ float wfs[64][65];
    __shared__ float wms[64][65];
    int tid = threadIdx.x;
    for (int idx = tid; idx < 4096; idx += 256) {
        int r = idx >> 6, d = idx & 63;
        wfs[r][d] = wf[r * CQ + h * 64 + d];
        wms[r][d] = wm[r * CQ + h * 64 + d];
    }
    __syncthreads();
    for (int idx = tid; idx < 4096; idx += 256) {
        int i = idx >> 6, j = idx & 63;
        float s = 0.f;
        #pragma unroll
        for (int d = 0; d < 64; d++) s += wfs[i][d] * wms[j][d];
        g_G[i * CQ + h * 64 + j] = s;
    }
    if (tid < 64) {
        float s = 0.f;
        #pragma unroll
        for (int d = 0; d < 64; d++) s += wms[tid][d] * bf[h * 64 + d];
        g_u[h * 64 + tid] = s;
    }
}

// ---------------- kernel 1: LayerNorm ----------------
__global__ __launch_bounds__(128) void ln_kernel(
    const float* __restrict__ src,
    const float* __restrict__ gamma, const float* __restrict__ beta,
    int which)
{
    __shared__ float gs[64], bs[64];
    int tid = threadIdx.x;
    if (tid < 64) { gs[tid] = gamma[tid]; bs[tid] = beta[tid]; }
    __syncthreads();

    int p = blockIdx.x * 128 + tid;
    float v[64];
    float mean = 0.f;
    #pragma unroll
    for (int c = 0; c < 64; c++) { v[c] = src[c * NPTS + p]; mean += v[c]; }
    mean *= (1.f / 64.f);
    float var = 0.f;
    #pragma unroll
    for (int c = 0; c < 64; c++) { float d = v[c] - mean; var += d * d; }
    float rstd = rsqrtf(var * (1.f / 64.f) + LNEPS);

    float* dst = which ? g_xm : g_xf;
    #pragma unroll
    for (int c = 0; c < 64; c += 4) {
        float4 o;
        o.x = (v[c + 0] - mean) * rstd * gs[c + 0] + bs[c + 0];
        o.y = (v[c + 1] - mean) * rstd * gs[c + 1] + bs[c + 1];
        o.z = (v[c + 2] - mean) * rstd * gs[c + 2] + bs[c + 2];
        o.w = (v[c + 3] - mean) * rstd * gs[c + 3] + bs[c + 3];
        *(float4*)&dst[p * 64 + c] = o;
    }
}

// ---------------- kernel 2: qm GEMM  [32768,64] x [64,1024], FFMA2 ----------------
// BM=128, BN=128, K=64, 256 threads, 8x8 thread tile, M-pair packed accumulators.
extern __shared__ float smemG[];   // As[64][128] then Bs[64][128]  (64 KB)
__global__ __launch_bounds__(256, 2) void qm_gemm_kernel()
{
    float* As = smemG;              // As[k*128 + m]
    float* Bs = smemG + 64 * 128;   // Bs[k*128 + n]
    int tid = threadIdx.x;
    int n0 = blockIdx.x * 128;
    int p0 = blockIdx.y * 128;

    // load A tile (transpose [p][c] -> [c][m])
    {
        int r  = tid & 127;
        int cb = (tid >> 7) * 32;
        #pragma unroll
        for (int i = 0; i < 8; i++) {
            float4 a = *(const float4*)&g_xf[(p0 + r) * 64 + cb + i * 4];
            As[(cb + i * 4 + 0) * 128 + r] = a.x;
            As[(cb + i * 4 + 1) * 128 + r] = a.y;
            As[(cb + i * 4 + 2) * 128 + r] = a.z;
            As[(cb + i * 4 + 3) * 128 + r] = a.w;
        }
    }
    // load B tile 64x128
    #pragma unroll
    for (int f = 0; f < 8; f++) {
        int idx = tid + f * 256;          // float4 index within 64x128 tile
        int c = idx >> 5, n = (idx & 31) * 4;
        *(float4*)&Bs[c * 128 + n] = *(const float4*)&g_G[c * CQ + n0 + n];
    }
    __syncthreads();

    int tx = tid & 15;        // n block (8 cols)
    int ty = tid >> 4;        // m block (8 rows)
    ull acc[4][8];            // acc[i][j] = { (m=ty*8+2i, n), (m=ty*8+2i+1, n) }
    #pragma unroll
    for (int i = 0; i < 4; i++)
        #pragma unroll
        for (int j = 0; j < 8; j++) acc[i][j] = 0ull;

    #pragma unroll 4
    for (int k = 0; k < 64; k++) {
        ull ap[4];
        #pragma unroll
        for (int i = 0; i < 4; i++)
            ap[i] = *(const ull*)&As[k * 128 + ty * 8 + 2 * i];
        float4 b0 = *(float4*)&Bs[k * 128 + tx * 8];
        float4 b1 = *(float4*)&Bs[k * 128 + tx * 8 + 4];
        ull bd[8];
        bd[0] = pack2(b0.x, b0.x); bd[1] = pack2(b0.y, b0.y);
        bd[2] = pack2(b0.z, b0.z); bd[3] = pack2(b0.w, b0.w);
        bd[4] = pack2(b1.x, b1.x); bd[5] = pack2(b1.y, b1.y);
        bd[6] = pack2(b1.z, b1.z); bd[7] = pack2(b1.w, b1.w);
        #pragma unroll
        for (int i = 0; i < 4; i++)
            #pragma unroll
            for (int j = 0; j < 8; j++)
                fma2(acc[i][j], ap[i], bd[j]);
    }

    // epilogue: += u, write chunked layout [(h*16+c4)][p]
    int nbase = n0 + tx * 8;              // 8 consecutive n, within one head
    int hq  = nbase >> 6;
    int c4a = (nbase & 63) >> 2;          // two consecutive c4 chunks
    float u0 = g_u[nbase + 0], u1 = g_u[nbase + 1], u2 = g_u[nbase + 2], u3 = g_u[nbase + 3];
    float u4 = g_u[nbase + 4], u5 = g_u[nbase + 5], u6 = g_u[nbase + 6], u7 = g_u[nbase + 7];
    float4* outp = (float4*)g_qm;
    long pl0 = (long)(hq * 16 + c4a) * NPTS;
    long pl1 = (long)(hq * 16 + c4a + 1) * NPTS;
    #pragma unroll
    for (int i = 0; i < 4; i++) {
        float2 r0 = unpack2(acc[i][0]), r1 = unpack2(acc[i][1]);
        float2 r2 = unpack2(acc[i][2]), r3 = unpack2(acc[i][3]);
        float2 r4 = unpack2(acc[i][4]), r5 = unpack2(acc[i][5]);
        float2 r6 = unpack2(acc[i][6]), r7 = unpack2(acc[i][7]);
        int pA = p0 + ty * 8 + 2 * i;
        int pB = pA + 1;
        outp[pl0 + pA] = make_float4(r0.x + u0, r1.x + u1, r2.x + u2, r3.x + u3);
        outp[pl1 + pA] = make_float4(r4.x + u4, r5.x + u5, r6.x + u6, r7.x + u7);
        outp[pl0 + pB] = make_float4(r0.y + u0, r1.y + u1, r2.y + u2, r3.y + u3);
        outp[pl1 + pB] = make_float4(r4.y + u4, r5.y + u5, r6.y + u6, r7.y + u7);
    }
}

// ---------------- kernel 3: neighborhood attention, head-pair FFMA2 ----------------
__global__ __launch_bounds__(256) void attn_kernel(
    const float* __restrict__ rpb, float* __restrict__ out)
{
    extern __shared__ float4 halo[];    // [c4=16][hz=4][hy=4][ht=34]
    __shared__ float rpb_s[NHD * 27];

    int tid = threadIdx.x;
    int z0 = (blockIdx.x >> 4) * 2;
    int y0 = (blockIdx.x & 15) * 2;

    for (int i = tid; i < NHD * 27; i += 256) rpb_s[i] = rpb[i];

    const float4* xm4 = (const float4*)g_xm;
    #pragma unroll 1
    for (int c4 = 0; c4 < 16; c4++) {
        for (int ptI = tid; ptI < 544; ptI += 256) {
            int hz = ptI / 136;
            int r  = ptI - hz * 136;
            int hy = r / 34;
            int ht = r - hy * 34;
            int gz = z0 - 1 + hz, gy = y0 - 1 + hy, gt = ht - 1;
            float4 v = make_float4(0.f, 0.f, 0.f, 0.f);
            if ((unsigned)gz < 32u && (unsigned)gy < 32u && (unsigned)gt < 32u)
                v = xm4[(gz * 1024 + gy * 32 + gt) * 16 + c4];
            halo[((c4 * 4 + hz) * 4 + hy) * 34 + ht] = v;
        }
    }
    __syncthreads();

    int half = tid >> 7;
    int ptid = tid & 127;
    int pz = ptid >> 6, py = (ptid >> 5) & 1, pt = ptid & 31;
    int gp = (z0 + pz) * 1024 + (y0 + py) * 32 + pt;
    const float4* qm4 = (const float4*)g_qm;

    #pragma unroll 1
    for (int hg = 0; hg < 2; hg++) {
        int h0 = half * 8 + hg * 4;

        // f32x2 accumulators: sc2[pr][off] = {score[h0+2pr], score[h0+2pr+1]}
        ull sc2[2][27];
        #pragma unroll
        for (int pr = 0; pr < 2; pr++)
            #pragma unroll
            for (int o = 0; o < 27; o++) sc2[pr][o] = 0ull;

        float4 qv[4], qvn[4];
        #pragma unroll
        for (int hh = 0; hh < 4; hh++)
            qv[hh] = qm4[((h0 + hh) * 16 + 0) * NPTS + gp];

        #pragma unroll 1
        for (int c4 = 0; c4 < 16; c4++) {
            if (c4 < 15) {
                #pragma unroll
                for (int hh = 0; hh < 4; hh++)
                    qvn[hh] = qm4[((h0 + hh) * 16 + (c4 + 1)) * NPTS + gp];
            }
            // pack q head-pairs per component (amortized over 27 offsets)
            ull qp[2][4];
            #pragma unroll
            for (int pr = 0; pr < 2; pr++) {
                qp[pr][0] = pack2(qv[2 * pr].x, qv[2 * pr + 1].x);
                qp[pr][1] = pack2(qv[2 * pr].y, qv[2 * pr + 1].y);
                qp[pr][2] = pack2(qv[2 * pr].z, qv[2 * pr + 1].z);
                qp[pr][3] = pack2(qv[2 * pr].w, qv[2 * pr + 1].w);
            }
            #pragma unroll
            for (int dz = 0; dz < 3; dz++)
                #pragma unroll
                for (int dy = 0; dy < 3; dy++)
                    #pragma unroll
                    for (int dx = 0; dx < 3; dx++) {
                        float4 kv = halo[((c4 * 4 + pz + dz) * 4 + (py + dy)) * 34 + (pt + dx)];
                        int off = (dz * 3 + dy) * 3 + dx;
                        ull kd;
                        kd = pack2(kv.x, kv.x);
                        fma2(sc2[0][off], qp[0][0], kd);
                        fma2(sc2[1][off], qp[1][0], kd);
                        kd = pack2(kv.y, kv.y);
                        fma2(sc2[0][off], qp[0][1], kd);
                        fma2(sc2[1][off], qp[1][1], kd);
                        kd = pack2(kv.z, kv.z);
                        fma2(sc2[0][off], qp[0][2], kd);
                        fma2(sc2[1][off], qp[1][2], kd);
                        kd = pack2(kv.w, kv.w);
                        fma2(sc2[0][off], qp[0][3], kd);
                        fma2(sc2[1][off], qp[1][3], kd);
                    }
            #pragma unroll
            for (int hh = 0; hh < 4; hh++) qv[hh] = qvn[hh];
        }

        // epilogue: unpack, add rpb, softmax, value-grid projection
        #pragma unroll
        for (int pr = 0; pr < 2; pr++) {
            float s0[27], s1[27];
            int hA = h0 + 2 * pr, hB = hA + 1;
            #pragma unroll
            for (int o = 0; o < 27; o++) {
                float2 v = unpack2(sc2[pr][o]);
                s0[o] = v.x + rpb_s[hA * 27 + o];
                s1[o] = v.y + rpb_s[hB * 27 + o];
            }
            #pragma unroll
            for (int w = 0; w < 2; w++) {
                const float* s = w ? s1 : s0;
                int h = w ? hB : hA;
                float m = s[0];
                #pragma unroll
                for (int o = 1; o < 27; o++) m = fmaxf(m, s[o]);
                float sum = 0.f, xz = 0.f, xy = 0.f, xt = 0.f;
                #pragma unroll
                for (int dz = 0; dz < 3; dz++)
                    #pragma unroll
                    for (int dy = 0; dy < 3; dy++)
                        #pragma unroll
                        for (int dx = 0; dx < 3; dx++) {
                            int o = (dz * 3 + dy) * 3 + dx;
                            float e = __expf(s[o] - m);
                            sum += e;
                            xz += e * (float)(dz - 1);
                            xy += e * (float)(dy - 1);
                            xt += e * (float)(dx - 1);
                        }
                float inv = 1.f / sum;
                out[(h * 3 + 0) * NPTS + gp] = xz * inv;
                out[(h * 3 + 1) * NPTS + gp] = xy * inv;
                out[(h * 3 + 2) * NPTS + gp] = xt * inv;
            }
        }
    }
}

// ---------------- launch ----------------
extern "C" void kernel_launch(void* const* d_in, const int* in_sizes, int n_in,
                              void* d_out, int out_size)
{
    const float* F       = (const float*)d_in[0];
    const float* M       = (const float*)d_in[1];
    const float* gamma_f = (const float*)d_in[2];
    const float* beta_f  = (const float*)d_in[3];
    const float* w_f     = (const float*)d_in[4];
    const float* b_f     = (const float*)d_in[5];
    const float* gamma_m = (const float*)d_in[6];
    const float* beta_m  = (const float*)d_in[7];
    const float* w_m     = (const float*)d_in[8];
    /* b_m (d_in[9]) is softmax-invariant and drops out */
    const float* rpb     = (const float*)d_in[10];
    float* out = (float*)d_out;

    precompute_kernel<<<16, 256>>>(w_f, w_m, b_f);

    ln_kernel<<<NPTS / 128, 128>>>(F, gamma_f, beta_f, 0);
    ln_kernel<<<NPTS / 128, 128>>>(M, gamma_m, beta_m, 1);

    const int gemmSmem = 64 * 128 * 2 * (int)sizeof(float);   // 65536
    cudaFuncSetAttribute(qm_gemm_kernel, cudaFuncAttributeMaxDynamicSharedMemorySize, gemmSmem);
    qm_gemm_kernel<<<dim3(CQ / 128, NPTS / 128), 256, gemmSmem>>>();

    const int haloBytes = 16 * 4 * 4 * 34 * (int)sizeof(float4);   // 139264
    cudaFuncSetAttribute(attn_kernel, cudaFuncAttributeMaxDynamicSharedMemorySize, haloBytes);
    attn_kernel<<<256, 256, haloBytes>>>(rpb, out);
}

// round 4
// speedup vs baseline: 1.4860x; 1.4860x over previous
#include <cuda_runtime.h>
#include <cuda_bf16.h>
#include <cstdint>
#include <math.h>

#define NPTS  32768
#define CIN   64
#define NHD   16
#define CQ    1024
#define LNEPS 1e-5f

// ---------------- helpers ----------------
__device__ __forceinline__ uint32_t smem_u32(const void* p) {
    uint32_t a;
    asm("{ .reg .u64 t; cvta.to.shared.u64 t, %1; cvt.u32.u64 %0, t; }" : "=r"(a) : "l"(p));
    return a;
}
__device__ __forceinline__ void ldsm_x4(uint32_t r[4], uint32_t addr) {
    asm volatile("ldmatrix.sync.aligned.m8n8.x4.shared.b16 {%0,%1,%2,%3}, [%4];"
                 : "=r"(r[0]), "=r"(r[1]), "=r"(r[2]), "=r"(r[3]) : "r"(addr));
}
__device__ __forceinline__ void mma_bf16(float c[4], const uint32_t a[4], uint32_t b0, uint32_t b1) {
    asm volatile("mma.sync.aligned.m16n8k16.row.col.f32.bf16.bf16.f32 "
                 "{%0,%1,%2,%3}, {%4,%5,%6,%7}, {%8,%9}, {%0,%1,%2,%3};"
                 : "+f"(c[0]), "+f"(c[1]), "+f"(c[2]), "+f"(c[3])
                 : "r"(a[0]), "r"(a[1]), "r"(a[2]), "r"(a[3]), "r"(b0), "r"(b1));
}
__device__ __forceinline__ uint32_t pkb(__nv_bfloat16 a, __nv_bfloat16 b) {
    return (uint32_t)__bfloat16_as_ushort(a) | ((uint32_t)__bfloat16_as_ushort(b) << 16);
}

// ---------------- scratch ----------------
__device__ float    g_xm  [NPTS * CIN];     // LN(M) fp32, [p][c]
__device__ uint32_t g_xfh [NPTS * 64];      // LN(F) bf16 split, [p][word]: words 0-31 hi pairs, 32-63 lo pairs
__device__ float    g_qm  [NPTS * CQ];      // float2 planes: [(h*32+c2)][p][2]
__device__ uint32_t g_GtA [CQ * 64];        // [n][word]: [hi | lo]
__device__ uint32_t g_GtB [CQ * 64];        // [n][word]: [lo | hi]
__device__ float    g_u   [CQ];

// ---------------- kernel 0: fused weights G = Wf Wm^T (bf16 split) + u ----------------
__global__ __launch_bounds__(256) void precompute_kernel(
    const float* __restrict__ wf, const float* __restrict__ wm,
    const float* __restrict__ bf)
{
    int h = blockIdx.x;
    __shared__ float wfs[64][65];
    __shared__ float wms[64][65];
    int tid = threadIdx.x;
    for (int idx = tid; idx < 4096; idx += 256) {
        int r = idx >> 6, d = idx & 63;
        wfs[r][d] = wf[r * CQ + h * 64 + d];
        wms[r][d] = wm[r * CQ + h * 64 + d];
    }
    __syncthreads();
    for (int idx = tid; idx < 2048; idx += 256) {
        int i2 = idx >> 6, j = idx & 63;
        float s0 = 0.f, s1 = 0.f;
        #pragma unroll
        for (int d = 0; d < 64; d++) {
            s0 += wfs[2 * i2][d] * wms[j][d];
            s1 += wfs[2 * i2 + 1][d] * wms[j][d];
        }
        __nv_bfloat16 h0 = __float2bfloat16_rn(s0), h1 = __float2bfloat16_rn(s1);
        __nv_bfloat16 l0 = __float2bfloat16_rn(s0 - __bfloat162float(h0));
        __nv_bfloat16 l1 = __float2bfloat16_rn(s1 - __bfloat162float(h1));
        int n = h * 64 + j;
        uint32_t hp = pkb(h0, h1), lp = pkb(l0, l1);
        g_GtA[n * 64 + i2]      = hp;
        g_GtA[n * 64 + 32 + i2] = lp;
        g_GtB[n * 64 + i2]      = lp;
        g_GtB[n * 64 + 32 + i2] = hp;
    }
    if (tid < 64) {
        float s = 0.f;
        #pragma unroll
        for (int d = 0; d < 64; d++) s += wms[tid][d] * bf[h * 64 + d];
        g_u[h * 64 + tid] = s;
    }
}

// ---------------- kernel 1: LayerNorm ----------------
__global__ __launch_bounds__(128) void ln_kernel(
    const float* __restrict__ src,
    const float* __restrict__ gamma, const float* __restrict__ beta,
    int which)   // 0 -> bf16 split to g_xfh ; 1 -> fp32 to g_xm
{
    __shared__ float gs[64], bs[64];
    int tid = threadIdx.x;
    if (tid < 64) { gs[tid] = gamma[tid]; bs[tid] = beta[tid]; }
    __syncthreads();

    int p = blockIdx.x * 128 + tid;
    float v[64];
    float mean = 0.f;
    #pragma unroll
    for (int c = 0; c < 64; c++) { v[c] = src[c * NPTS + p]; mean += v[c]; }
    mean *= (1.f / 64.f);
    float var = 0.f;
    #pragma unroll
    for (int c = 0; c < 64; c++) { float d = v[c] - mean; var += d * d; }
    float rstd = rsqrtf(var * (1.f / 64.f) + LNEPS);

    if (which == 0) {
        #pragma unroll
        for (int c8 = 0; c8 < 64; c8 += 8) {
            uint32_t hw[4], lw[4];
            #pragma unroll
            for (int j = 0; j < 4; j++) {
                int c = c8 + 2 * j;
                float y0 = (v[c] - mean) * rstd * gs[c] + bs[c];
                float y1 = (v[c + 1] - mean) * rstd * gs[c + 1] + bs[c + 1];
                __nv_bfloat16 h0 = __float2bfloat16_rn(y0), h1 = __float2bfloat16_rn(y1);
                __nv_bfloat16 l0 = __float2bfloat16_rn(y0 - __bfloat162float(h0));
                __nv_bfloat16 l1 = __float2bfloat16_rn(y1 - __bfloat162float(h1));
                hw[j] = pkb(h0, h1);
                lw[j] = pkb(l0, l1);
            }
            *(uint4*)&g_xfh[p * 64 + (c8 >> 1)]      = make_uint4(hw[0], hw[1], hw[2], hw[3]);
            *(uint4*)&g_xfh[p * 64 + 32 + (c8 >> 1)] = make_uint4(lw[0], lw[1], lw[2], lw[3]);
        }
    } else {
        #pragma unroll
        for (int c = 0; c < 64; c += 4) {
            float4 o;
            o.x = (v[c + 0] - mean) * rstd * gs[c + 0] + bs[c + 0];
            o.y = (v[c + 1] - mean) * rstd * gs[c + 1] + bs[c + 1];
            o.z = (v[c + 2] - mean) * rstd * gs[c + 2] + bs[c + 2];
            o.w = (v[c + 3] - mean) * rstd * gs[c + 3] + bs[c + 3];
            *(float4*)&g_xm[p * 64 + c] = o;
        }
    }
}

// ---------------- kernel 2: qm GEMM via mma.sync bf16 (split, exact) ----------------
// CTA 128x128, K=128 per pass, 2 passes. 8 warps = 2(m) x 4(n), warp tile 64x32.
#define GEMM_SMEM (65536)

__global__ __launch_bounds__(256, 2) void qm_gemm_mma()
{
    extern __shared__ char smg[];      // A @0 (32KB), B @32768 (32KB)
    __shared__ float su[128];
    int tid = threadIdx.x;
    int wid = tid >> 5, lane = tid & 31;
    int n0 = blockIdx.x * 128;
    int p0 = blockIdx.y * 128;
    int wm = wid & 1, wn = wid >> 1;

    if (tid < 128) su[tid] = g_u[n0 + tid];

    // A tile: 128 rows x 256B, swizzled 16B chunks
    const uint4* xf4 = (const uint4*)g_xfh;     // [NPTS][16 chunks]
    #pragma unroll
    for (int i = tid; i < 2048; i += 256) {
        int r = i >> 4, c = i & 15;
        uint4 v = xf4[(p0 + r) * 16 + c];
        *(uint4*)(smg + r * 256 + ((c ^ (r & 7)) << 4)) = v;
    }

    float acc[4][4][4];
    #pragma unroll
    for (int mi = 0; mi < 4; mi++)
        #pragma unroll
        for (int ni = 0; ni < 4; ni++)
            #pragma unroll
            for (int e = 0; e < 4; e++) acc[mi][ni][e] = 0.f;

    // precomputed lane addressing
    int arow = wm * 64 + (lane & 15);
    int ach  = lane >> 4;
    int brow = wn * 32 + (lane & 7) + ((lane >> 4) << 3);
    int bch  = (lane >> 3) & 1;

    #pragma unroll
    for (int pass = 0; pass < 2; pass++) {
        const uint4* Gt = (const uint4*)(pass == 0 ? g_GtA : g_GtB);
        __syncthreads();
        #pragma unroll
        for (int i = tid; i < 2048; i += 256) {
            int r = i >> 4, c = i & 15;
            uint4 v = Gt[(n0 + r) * 16 + c];
            *(uint4*)(smg + 32768 + r * 256 + ((c ^ (r & 7)) << 4)) = v;
        }
        __syncthreads();

        #pragma unroll
        for (int ks = 0; ks < 8; ks++) {
            uint32_t a[4][4];
            #pragma unroll
            for (int mi = 0; mi < 4; mi++) {
                int row = arow + mi * 16;
                int ch  = ks * 2 + ach;
                ldsm_x4(a[mi], smem_u32(smg + row * 256 + ((ch ^ (row & 7)) << 4)));
            }
            uint32_t b[2][4];
            #pragma unroll
            for (int nj = 0; nj < 2; nj++) {
                int row = brow + nj * 16;
                int ch  = ks * 2 + bch;
                ldsm_x4(b[nj], smem_u32(smg + 32768 + row * 256 + ((ch ^ (row & 7)) << 4)));
            }
            #pragma unroll
            for (int mi = 0; mi < 4; mi++)
                #pragma unroll
                for (int nj = 0; nj < 2; nj++) {
                    mma_bf16(acc[mi][2 * nj + 0], a[mi], b[nj][0], b[nj][1]);
                    mma_bf16(acc[mi][2 * nj + 1], a[mi], b[nj][2], b[nj][3]);
                }
        }
    }

    // epilogue: += u, store float2 planes [(h*32+c2)][p]
    int g = lane >> 2, t = lane & 3;
    float2* q2 = (float2*)g_qm;
    #pragma unroll
    for (int mi = 0; mi < 4; mi++) {
        int pA = p0 + wm * 64 + mi * 16 + g;
        #pragma unroll
        for (int ni = 0; ni < 4; ni++) {
            int nl = wn * 32 + ni * 8 + 2 * t;
            int ng = n0 + nl;
            int h = ng >> 6, c2 = (ng & 63) >> 1;
            long base = (long)(h * 32 + c2) * NPTS;
            float u0 = su[nl], u1 = su[nl + 1];
            q2[base + pA]     = make_float2(acc[mi][ni][0] + u0, acc[mi][ni][1] + u1);
            q2[base + pA + 8] = make_float2(acc[mi][ni][2] + u0, acc[mi][ni][3] + u1);
        }
    }
}

// ---------------- kernel 3: neighborhood attention (512 thr, 2 heads/thread) ----------------
__global__ __launch_bounds__(512) void attn_kernel(
    const float* __restrict__ rpb, float* __restrict__ out)
{
    extern __shared__ float4 halo[];    // [c4=16][hz=4][hy=4][ht=34]
    __shared__ float rpb_s[NHD * 27];

    int tid = threadIdx.x;
    int z0 = (blockIdx.x >> 4) * 2;
    int y0 = (blockIdx.x & 15) * 2;

    for (int i = tid; i < NHD * 27; i += 512) rpb_s[i] = rpb[i];

    const float4* xm4 = (const float4*)g_xm;
    for (int i = tid; i < 8704; i += 512) {
        int c4 = i / 544;
        int r  = i - c4 * 544;
        int hz = r / 136;
        int r2 = r - hz * 136;
        int hy = r2 / 34;
        int ht = r2 - hy * 34;
        int gz = z0 - 1 + hz, gy = y0 - 1 + hy, gt = ht - 1;
        float4 v = make_float4(0.f, 0.f, 0.f, 0.f);
        if ((unsigned)gz < 32u && (unsigned)gy < 32u && (unsigned)gt < 32u)
            v = xm4[(gz * 1024 + gy * 32 + gt) * 16 + c4];
        halo[((c4 * 4 + hz) * 4 + hy) * 34 + ht] = v;
    }
    __syncthreads();

    int quarter = tid >> 7;
    int ptid = tid & 127;
    int pz = ptid >> 6, py = (ptid >> 5) & 1, pt = ptid & 31;
    int gp = (z0 + pz) * 1024 + (y0 + py) * 32 + pt;
    const float2* qm2 = (const float2*)g_qm;

    #pragma unroll 1
    for (int hg = 0; hg < 2; hg++) {
        int h0 = 2 * (quarter + 4 * hg);    // head pair {h0, h0+1}

        float sc0[27], sc1[27];
        #pragma unroll
        for (int o = 0; o < 27; o++) {
            sc0[o] = rpb_s[h0 * 27 + o];
            sc1[o] = rpb_s[(h0 + 1) * 27 + o];
        }

        float2 a0 = qm2[(h0 * 32 + 0) * NPTS + gp];
        float2 a1 = qm2[(h0 * 32 + 1) * NPTS + gp];
        float2 b0 = qm2[((h0 + 1) * 32 + 0) * NPTS + gp];
        float2 b1 = qm2[((h0 + 1) * 32 + 1) * NPTS + gp];
        float4 q0 = make_float4(a0.x, a0.y, a1.x, a1.y);
        float4 q1 = make_float4(b0.x, b0.y, b1.x, b1.y);
        float4 q0n, q1n;

        #pragma unroll 1
        for (int c4 = 0; c4 < 16; c4++) {
            if (c4 < 15) {
                float2 c0 = qm2[(h0 * 32 + 2 * c4 + 2) * NPTS + gp];
                float2 c1 = qm2[(h0 * 32 + 2 * c4 + 3) * NPTS + gp];
                float2 d0 = qm2[((h0 + 1) * 32 + 2 * c4 + 2) * NPTS + gp];
                float2 d1 = qm2[((h0 + 1) * 32 + 2 * c4 + 3) * NPTS + gp];
                q0n = make_float4(c0.x, c0.y, c1.x, c1.y);
                q1n = make_float4(d0.x, d0.y, d1.x, d1.y);
            }
            #pragma unroll
            for (int dz = 0; dz < 3; dz++)
                #pragma unroll
                for (int dy = 0; dy < 3; dy++)
                    #pragma unroll
                    for (int dx = 0; dx < 3; dx++) {
                        float4 kv = halo[((c4 * 4 + pz + dz) * 4 + (py + dy)) * 34 + (pt + dx)];
                        int off = (dz * 3 + dy) * 3 + dx;
                        sc0[off] = fmaf(q0.x, kv.x, sc0[off]);
                        sc0[off] = fmaf(q0.y, kv.y, sc0[off]);
                        sc0[off] = fmaf(q0.z, kv.z, sc0[off]);
                        sc0[off] = fmaf(q0.w, kv.w, sc0[off]);
                        sc1[off] = fmaf(q1.x, kv.x, sc1[off]);
                        sc1[off] = fmaf(q1.y, kv.y, sc1[off]);
                        sc1[off] = fmaf(q1.z, kv.z, sc1[off]);
                        sc1[off] = fmaf(q1.w, kv.w, sc1[off]);
                    }
            q0 = q0n; q1 = q1n;
        }

        #pragma unroll
        for (int w = 0; w < 2; w++) {
            const float* s = w ? sc1 : sc0;
            int h = h0 + w;
            float m = s[0];
            #pragma unroll
            for (int o = 1; o < 27; o++) m = fmaxf(m, s[o]);
            float sum = 0.f, xz = 0.f, xy = 0.f, xt = 0.f;
            #pragma unroll
            for (int dz = 0; dz < 3; dz++)
                #pragma unroll
                for (int dy = 0; dy < 3; dy++)
                    #pragma unroll
                    for (int dx = 0; dx < 3; dx++) {
                        int o = (dz * 3 + dy) * 3 + dx;
                        float e = __expf(s[o] - m);
                        sum += e;
                        xz += e * (float)(dz - 1);
                        xy += e * (float)(dy - 1);
                        xt += e * (float)(dx - 1);
                    }
            float inv = 1.f / sum;
            out[(h * 3 + 0) * NPTS + gp] = xz * inv;
            out[(h * 3 + 1) * NPTS + gp] = xy * inv;
            out[(h * 3 + 2) * NPTS + gp] = xt * inv;
        }
    }
}

// ---------------- launch ----------------
extern "C" void kernel_launch(void* const* d_in, const int* in_sizes, int n_in,
                              void* d_out, int out_size)
{
    const float* F       = (const float*)d_in[0];
    const float* M       = (const float*)d_in[1];
    const float* gamma_f = (const float*)d_in[2];
    const float* beta_f  = (const float*)d_in[3];
    const float* w_f     = (const float*)d_in[4];
    const float* b_f     = (const float*)d_in[5];
    const float* gamma_m = (const float*)d_in[6];
    const float* beta_m  = (const float*)d_in[7];
    const float* w_m     = (const float*)d_in[8];
    /* b_m (d_in[9]) is softmax-invariant and drops out */
    const float* rpb     = (const float*)d_in[10];
    float* out = (float*)d_out;

    precompute_kernel<<<16, 256>>>(w_f, w_m, b_f);
    ln_kernel<<<NPTS / 128, 128>>>(F, gamma_f, beta_f, 0);
    ln_kernel<<<NPTS / 128, 128>>>(M, gamma_m, beta_m, 1);

    cudaFuncSetAttribute(qm_gemm_mma, cudaFuncAttributeMaxDynamicSharedMemorySize, GEMM_SMEM);
    qm_gemm_mma<<<dim3(8, 256), 256, GEMM_SMEM>>>();

    const int haloBytes = 16 * 4 * 4 * 34 * (int)sizeof(float4);   // 139264
    cudaFuncSetAttribute(attn_kernel, cudaFuncAttributeMaxDynamicSharedMemorySize, haloBytes);
    attn_kernel<<<256, 512, haloBytes>>>(rpb, out);
}